// round 8
// baseline (speedup 1.0000x reference)
#include <cuda_runtime.h>
#include <cstdint>

// CutStripes: out[b,c,t,f] = mask(b,t) ? x[perm[b],c,t,f] : x[b,c,t,f]
// x (128,1,2048,128) f32; perm (128) i32; bgn,distance (128,4) i32.
//
// Persistent grid-stride version: one wave of CTAs (148 SMs x 8), each
// looping over 1024-float4 slabs with the MLP=4 front-batched body that
// measured best (R2). Removes the 6 wave transitions of the 7-wave
// launch. Each slab lies fully inside one batch b, so stripe params are
// uniform per iteration (L1-resident reloads).

static constexpr int T  = 2048;
static constexpr long TOTAL4 = 128L * 2048L * 32L;   // 8,388,608 float4
static constexpr int ITEMS = 4;
static constexpr int THREADS = 256;
static constexpr int SLAB = THREADS * ITEMS;         // 1024 float4
static constexpr int NSLABS = (int)(TOTAL4 / SLAB);  // 8192
static constexpr int GRID = 148 * 8;                 // one full wave

__global__ void __launch_bounds__(THREADS, 8)
cutstripes_persistent_kernel(const float4* __restrict__ x,
                             const int*    __restrict__ perm,
                             const int*    __restrict__ bgn,
                             const int*    __restrict__ dist,
                             float4*       __restrict__ out)
{
    const unsigned tid = threadIdx.x;

    for (unsigned slab = blockIdx.x; slab < (unsigned)NSLABS; slab += GRID) {
        const unsigned base = slab * SLAB + tid;
        const int b = (int)(slab >> 6);             // (slab*1024) >> 16

        // Slab-uniform stripe params + permuted batch (L1-resident).
        const int4 bg = __ldg((const int4*)(bgn  + (b << 2)));
        const int4 ds = __ldg((const int4*)(dist + (b << 2)));
        const int  pb = __ldg(perm + b);

        unsigned idx[ITEMS];
        unsigned src[ITEMS];
#pragma unroll
        for (int k = 0; k < ITEMS; k++) {
            idx[k] = base + k * THREADS;
            const int t = (idx[k] >> 5) & (T - 1);
            const bool m = ((unsigned)(t - bg.x) < (unsigned)ds.x) |
                           ((unsigned)(t - bg.y) < (unsigned)ds.y) |
                           ((unsigned)(t - bg.z) < (unsigned)ds.z) |
                           ((unsigned)(t - bg.w) < (unsigned)ds.w);
            const int src_b = m ? pb : b;
            src[k] = ((unsigned)src_b << 16) | (idx[k] & 0xFFFFu);
        }

        // Front-batched loads: 4 outstanding 128B LDGs per thread.
        float4 v[ITEMS];
#pragma unroll
        for (int k = 0; k < ITEMS; k++)
            v[k] = __ldcs(x + src[k]);      // streaming: no reuse

#pragma unroll
        for (int k = 0; k < ITEMS; k++)
            __stcs(out + idx[k], v[k]);     // streaming store
    }
}

extern "C" void kernel_launch(void* const* d_in, const int* in_sizes, int n_in,
                              void* d_out, int out_size)
{
    const float4* x    = (const float4*)d_in[0];
    const int*    perm = (const int*)   d_in[1];
    const int*    bgn  = (const int*)   d_in[2];
    const int*    dist = (const int*)   d_in[3];
    float4*       out  = (float4*)      d_out;

    cutstripes_persistent_kernel<<<GRID, THREADS>>>(x, perm, bgn, dist, out);
}

// round 9
// speedup vs baseline: 1.0908x; 1.0908x over previous
#include <cuda_runtime.h>
#include <cstdint>

// CutStripes: out[b,c,t,f] = mask(b,t) ? x[perm[b],c,t,f] : x[b,c,t,f]
// x (128,1,2048,128) f32; perm (128) i32; bgn,distance (128,4) i32.
//
// Best-measured configuration (R2): flat launch, MLP=4 per thread.
// Each thread owns 4 float4 at stride 256 within a 1024-float4 block
// slab; all 4 source addresses computed first, then 4 front-batched
// 128-bit loads, then 4 stores. A slab lies fully inside one batch b
// (65536 float4 per b, 1024-aligned), so stripe params + perm are
// block-uniform L1-resident loads.
//
// Session evidence: app throughput 268MB / 37.7us = 7.1 TB/s (~89% of
// HBM spec) — at roofline. MLP=8 (R4/R5) and persistent single-wave
// (R8) both regressed: MLP-vs-registers trade peaks at ITEMS=4, and
// wave transitions are already hidden by the scheduler.

static constexpr int T  = 2048;
static constexpr long TOTAL4 = 128L * 2048L * 32L;   // 8,388,608 float4
static constexpr int ITEMS = 4;
static constexpr int THREADS = 256;

__global__ void __launch_bounds__(THREADS)
cutstripes_kernel(const float4* __restrict__ x,
                  const int*    __restrict__ perm,
                  const int*    __restrict__ bgn,
                  const int*    __restrict__ dist,
                  float4*       __restrict__ out)
{
    // Block slab: 1024 consecutive float4. b uniform across the block.
    const unsigned base = blockIdx.x * (THREADS * ITEMS) + threadIdx.x;
    const int b = blockIdx.x >> 6;                 // (blk*1024) >> 16

    // Block-uniform stripe params + permuted batch (L1-resident).
    const int4 bg = __ldg((const int4*)(bgn  + (b << 2)));
    const int4 ds = __ldg((const int4*)(dist + (b << 2)));
    const int  pb = __ldg(perm + b);

    unsigned idx[ITEMS];
    unsigned src[ITEMS];
#pragma unroll
    for (int k = 0; k < ITEMS; k++) {
        idx[k] = base + k * THREADS;
        const int t = (idx[k] >> 5) & (T - 1);
        const bool m = ((unsigned)(t - bg.x) < (unsigned)ds.x) |
                       ((unsigned)(t - bg.y) < (unsigned)ds.y) |
                       ((unsigned)(t - bg.z) < (unsigned)ds.z) |
                       ((unsigned)(t - bg.w) < (unsigned)ds.w);
        const int src_b = m ? pb : b;
        src[k] = ((unsigned)src_b << 16) | (idx[k] & 0xFFFFu);
    }

    // Front-batched loads: 4 outstanding 128B LDGs per thread.
    float4 v[ITEMS];
#pragma unroll
    for (int k = 0; k < ITEMS; k++)
        v[k] = __ldcs(x + src[k]);          // streaming: no reuse

#pragma unroll
    for (int k = 0; k < ITEMS; k++)
        __stcs(out + idx[k], v[k]);         // streaming store
}

extern "C" void kernel_launch(void* const* d_in, const int* in_sizes, int n_in,
                              void* d_out, int out_size)
{
    const float4* x    = (const float4*)d_in[0];
    const int*    perm = (const int*)   d_in[1];
    const int*    bgn  = (const int*)   d_in[2];
    const int*    dist = (const int*)   d_in[3];
    float4*       out  = (float4*)      d_out;

    const int blocks = (int)(TOTAL4 / (THREADS * ITEMS));   // 8192
    cutstripes_kernel<<<blocks, THREADS>>>(x, perm, bgn, dist, out);
}